// round 2
// baseline (speedup 1.0000x reference)
#include <cuda_runtime.h>
#include <cfloat>

// xp: (32, 64, 64, 512) fp32, m innermost. out: (32, 48*512), bin = iw*6+ih.
// Resize is identity. Row bins: 8 rows each. Col edges: {0,11,21,32,43,53,64}.
//
// R2 change vs R1: force <=46 regs so all 1536 blocks are resident in a single
// wave (11+ blocks/SM; R1's 60 regs capped residency at 8 blocks/SM -> a
// straggler second wave of 352 blocks at ~30% machine fill). Column unroll
// reduced 11 -> 4 to cut live registers and L1tex-queue front-batching (CTA
// spread), while keeping MLP=4 per warp (ample for DRAM latency hiding).

#define B_DIM 32
#define W_DIM 64
#define H_DIM 64
#define M_DIM 512
#define W_BINS 8
#define H_BINS 6
#define M4 (M_DIM / 4)   // 128 float4 lanes per (b,r,c)

__constant__ int C_EDGE[H_BINS + 1] = {0, 11, 21, 32, 43, 53, 64};

static __device__ __forceinline__ float4 fmax4(float4 a, float4 b) {
    a.x = fmaxf(a.x, b.x);
    a.y = fmaxf(a.y, b.y);
    a.z = fmaxf(a.z, b.z);
    a.w = fmaxf(a.w, b.w);
    return a;
}

// One block per (batch, bin). 128 threads; thread t owns channels [4t, 4t+4).
// Per (r,c) the block loads 128 * 16B = 2KB contiguous -> fully coalesced.
__global__ __launch_bounds__(M4, 11)
void adaptive_maxpool_kernel(const float4* __restrict__ x4, float4* __restrict__ out4) {
    const int bin = blockIdx.x;       // 0..47  (iw*6 + ih)
    const int b   = blockIdx.y;       // 0..31
    const int iw  = bin / H_BINS;
    const int ih  = bin - iw * H_BINS;

    const int r1 = iw * (W_DIM / W_BINS);          // 8 rows per bin
    const int c1 = C_EDGE[ih];
    const int nc = C_EDGE[ih + 1] - c1;            // 10 or 11

    const int t = threadIdx.x;                     // 0..127
    const float4* base =
        x4 + ((size_t)(b * W_DIM + r1) * H_DIM + c1) * M4 + t;

    float4 acc = make_float4(-FLT_MAX, -FLT_MAX, -FLT_MAX, -FLT_MAX);

    for (int r = 0; r < 8; ++r) {
        const float4* row = base + (size_t)r * (H_DIM * M4);

        // Main: chunks of 4 columns (MLP=4 per warp, modest reg pressure).
        int c = 0;
        for (; c + 4 <= nc; c += 4) {
            float4 v0 = __ldg(row + (size_t)(c + 0) * M4);
            float4 v1 = __ldg(row + (size_t)(c + 1) * M4);
            float4 v2 = __ldg(row + (size_t)(c + 2) * M4);
            float4 v3 = __ldg(row + (size_t)(c + 3) * M4);
            acc = fmax4(acc, fmax4(fmax4(v0, v1), fmax4(v2, v3)));
        }
        // Remainder: 2 or 3 columns (nc is 10 or 11).
        if (c + 2 <= nc) {
            float4 v0 = __ldg(row + (size_t)(c + 0) * M4);
            float4 v1 = __ldg(row + (size_t)(c + 1) * M4);
            acc = fmax4(acc, fmax4(v0, v1));
            c += 2;
        }
        if (c < nc) {
            acc = fmax4(acc, __ldg(row + (size_t)c * M4));
        }
    }

    out4[((size_t)b * (W_BINS * H_BINS) + bin) * M4 + t] = acc;
}

extern "C" void kernel_launch(void* const* d_in, const int* in_sizes, int n_in,
                              void* d_out, int out_size) {
    (void)in_sizes; (void)n_in; (void)out_size;
    const float4* x4 = (const float4*)d_in[0];
    float4* o4 = (float4*)d_out;

    dim3 grid(W_BINS * H_BINS, B_DIM);   // (48, 32) = 1536 blocks
    adaptive_maxpool_kernel<<<grid, M4>>>(x4, o4);
}

// round 3
// speedup vs baseline: 1.0407x; 1.0407x over previous
#include <cuda_runtime.h>
#include <cfloat>

// xp: (32, 64, 64, 512) fp32, m innermost. out: (32, 48*512), bin = iw*6+ih.
// Resize is identity. Row bins: 8 rows each. Col edges: {0,11,21,32,43,53,64}.
//
// R3: evidence from R1/R2 says throughput tracks outstanding-LDG depth per SM,
// not occupancy. So: two-row interleaving + fully-unrolled columns (20-22
// independent LDG.E.128 streams per thread-iteration), reg cap 85 via
// __launch_bounds__(128, 6) -> ~430 loads in flight per SM (R1: ~350).
// __ldcs: read-once data, evict-first in L2.

#define B_DIM 32
#define W_DIM 64
#define H_DIM 64
#define M_DIM 512
#define W_BINS 8
#define H_BINS 6
#define M4 (M_DIM / 4)            // 128 float4 lanes per (b,r,c)
#define ROW_STRIDE (H_DIM * M4)   // float4 elems per image row

__constant__ int C_EDGE[H_BINS + 1] = {0, 11, 21, 32, 43, 53, 64};

static __device__ __forceinline__ float4 fmax4(float4 a, float4 b) {
    a.x = fmaxf(a.x, b.x);
    a.y = fmaxf(a.y, b.y);
    a.z = fmaxf(a.z, b.z);
    a.w = fmaxf(a.w, b.w);
    return a;
}

static __device__ __forceinline__ float4 ldcs4(const float4* p) {
    return __ldcs(p);
}

// One block per (batch, bin). 128 threads; thread t owns channels [4t, 4t+4).
__global__ __launch_bounds__(M4, 6)
void adaptive_maxpool_kernel(const float4* __restrict__ x4, float4* __restrict__ out4) {
    const int bin = blockIdx.x;       // 0..47  (iw*6 + ih)
    const int b   = blockIdx.y;       // 0..31
    const int iw  = bin / H_BINS;
    const int ih  = bin - iw * H_BINS;

    const int r1 = iw * (W_DIM / W_BINS);          // 8 rows per bin
    const int c1 = C_EDGE[ih];
    const bool has11 = (C_EDGE[ih + 1] - c1) == 11; // widths are 10 or 11

    const int t = threadIdx.x;                     // 0..127
    const float4* base =
        x4 + ((size_t)(b * W_DIM + r1) * H_DIM + c1) * M4 + t;

    float4 acc = make_float4(-FLT_MAX, -FLT_MAX, -FLT_MAX, -FLT_MAX);

    // 8 rows as 4 row-pairs; per pair issue 2x10 (+2) independent loads.
    #pragma unroll 1
    for (int rp = 0; rp < 4; ++rp) {
        const float4* r0 = base + (size_t)(2 * rp) * ROW_STRIDE;
        const float4* r1p = r0 + ROW_STRIDE;

        #pragma unroll
        for (int c = 0; c < 10; ++c) {
            float4 va = ldcs4(r0  + (size_t)c * M4);
            float4 vb = ldcs4(r1p + (size_t)c * M4);
            acc = fmax4(acc, fmax4(va, vb));
        }
        if (has11) {
            float4 va = ldcs4(r0  + (size_t)10 * M4);
            float4 vb = ldcs4(r1p + (size_t)10 * M4);
            acc = fmax4(acc, fmax4(va, vb));
        }
    }

    out4[((size_t)b * (W_BINS * H_BINS) + bin) * M4 + t] = acc;
}

extern "C" void kernel_launch(void* const* d_in, const int* in_sizes, int n_in,
                              void* d_out, int out_size) {
    (void)in_sizes; (void)n_in; (void)out_size;
    const float4* x4 = (const float4*)d_in[0];
    float4* o4 = (float4*)d_out;

    dim3 grid(W_BINS * H_BINS, B_DIM);   // (48, 32) = 1536 blocks
    adaptive_maxpool_kernel<<<grid, M4>>>(x4, o4);
}